// round 1
// baseline (speedup 1.0000x reference)
#include <cuda_runtime.h>
#include <cstdint>

#define D 64
#define N_NODES_C  20000
#define N_HEDGES_C 400000

// Scratch for support = X @ W (allocation-free rule: __device__ globals)
__device__ float g_sup1[(size_t)N_NODES_C * D];
__device__ float g_sup2[(size_t)N_HEDGES_C * D];

// ---------------------------------------------------------------------------
// GEMM: out[M,64] = X[M,64] @ W[64,64], fp32. 32 rows per block, 256 threads.
// Each thread computes 1 row x 8 consecutive cols (float4-pair loads of W).
// ---------------------------------------------------------------------------
__global__ void gemm_xw(const float* __restrict__ X, const float* __restrict__ W,
                        float* __restrict__ out, int M) {
    __shared__ float Xs[32][D + 1];                 // +1 pad: kill bank conflicts
    __shared__ __align__(16) float Ws[D][D];
    int t  = threadIdx.x;
    int m0 = blockIdx.x * 32;

    for (int i = t; i < D * D; i += 256) Ws[i >> 6][i & 63] = W[i];
    for (int i = t; i < 32 * D; i += 256) {
        int r = i >> 6, k = i & 63;
        int row = m0 + r;
        Xs[r][k] = (row < M) ? X[(size_t)row * D + k] : 0.f;
    }
    __syncthreads();

    int row = t >> 3;            // 0..31
    int cg  = (t & 7) * 8;       // col group base: 0,8,...,56
    float acc[8] = {0.f, 0.f, 0.f, 0.f, 0.f, 0.f, 0.f, 0.f};
#pragma unroll
    for (int k = 0; k < D; k++) {
        float  x  = Xs[row][k];
        float4 w0 = *(const float4*)&Ws[k][cg];
        float4 w1 = *(const float4*)&Ws[k][cg + 4];
        acc[0] += x * w0.x; acc[1] += x * w0.y; acc[2] += x * w0.z; acc[3] += x * w0.w;
        acc[4] += x * w1.x; acc[5] += x * w1.y; acc[6] += x * w1.z; acc[7] += x * w1.w;
    }
    int grow = m0 + row;
    if (grow < M) {
        float4* o = (float4*)(out + (size_t)grow * D + cg);
        o[0] = make_float4(acc[0], acc[1], acc[2], acc[3]);
        o[1] = make_float4(acc[4], acc[5], acc[6], acc[7]);
    }
}

// ---------------------------------------------------------------------------
// COO SpMM scatter: out[row] += val * dense[col], 16 threads per nnz,
// each thread owns one float4 lane. Vector red (no-return atomic) to L2.
// ---------------------------------------------------------------------------
__global__ void spmm_atomic(const int* __restrict__ rows, const int* __restrict__ cols,
                            const float* __restrict__ vals, const float* __restrict__ dense,
                            float* __restrict__ out, int nnz) {
    long long idx = (long long)blockIdx.x * blockDim.x + threadIdx.x;
    int nz = (int)(idx >> 4);
    int l4 = (int)(idx & 15);
    if (nz >= nnz) return;

    int   r = __ldg(&rows[nz]);
    int   c = __ldg(&cols[nz]);
    float v = __ldg(&vals[nz]);

    float4 x = __ldg((const float4*)(dense + (size_t)c * D) + l4);
    float* dst = out + (size_t)r * D + (size_t)l4 * 4;
    asm volatile("red.global.add.v4.f32 [%0], {%1, %2, %3, %4};"
                 :: "l"(dst), "f"(v * x.x), "f"(v * x.y), "f"(v * x.z), "f"(v * x.w)
                 : "memory");
}

// ---------------------------------------------------------------------------
// Epilogue: out = relu(out) + bias (bias broadcast over 64 cols), float4.
// ---------------------------------------------------------------------------
__global__ void epilogue(float* __restrict__ out, const float* __restrict__ bias, int n4) {
    int i = blockIdx.x * blockDim.x + threadIdx.x;
    if (i >= n4) return;
    float4 v = ((const float4*)out)[i];
    float4 b = __ldg((const float4*)bias + (i & 15));   // 64 floats = 16 float4 per row
    v.x = fmaxf(v.x, 0.f) + b.x;
    v.y = fmaxf(v.y, 0.f) + b.y;
    v.z = fmaxf(v.z, 0.f) + b.z;
    v.w = fmaxf(v.w, 0.f) + b.w;
    ((float4*)out)[i] = v;
}

// ---------------------------------------------------------------------------
// Launch
// ---------------------------------------------------------------------------
extern "C" void kernel_launch(void* const* d_in, const int* in_sizes, int n_in,
                              void* d_out, int out_size) {
    const float* node_x = (const float*)d_in[0];
    const float* he_x   = (const float*)d_in[1];
    const int*   nrows  = (const int*)  d_in[2];
    const int*   ncols  = (const int*)  d_in[3];
    const float* nvals  = (const float*)d_in[4];
    const int*   hrows  = (const int*)  d_in[5];
    const int*   hcols  = (const int*)  d_in[6];
    const float* hvals  = (const float*)d_in[7];
    const float* W      = (const float*)d_in[8];
    const float* bias   = (const float*)d_in[9];

    int n_nodes = in_sizes[0] / D;
    int n_he    = in_sizes[1] / D;
    int nnz_n   = in_sizes[2];
    int nnz_h   = in_sizes[5];

    float* out  = (float*)d_out;
    float* out1 = out;
    float* out2 = out + (size_t)n_nodes * D;

    float *sup1 = nullptr, *sup2 = nullptr;
    cudaGetSymbolAddress((void**)&sup1, g_sup1);
    cudaGetSymbolAddress((void**)&sup2, g_sup2);

    // Output accumulators start at zero (harness poisons to 0xAA).
    cudaMemsetAsync(d_out, 0, (size_t)out_size * sizeof(float), 0);

    gemm_xw<<<(n_nodes + 31) / 32, 256>>>(node_x, W, sup1, n_nodes);
    gemm_xw<<<(n_he    + 31) / 32, 256>>>(he_x,   W, sup2, n_he);

    long long tn = (long long)nnz_n * 16;
    spmm_atomic<<<(int)((tn + 255) / 256), 256>>>(nrows, ncols, nvals, sup1, out1, nnz_n);
    long long th = (long long)nnz_h * 16;
    spmm_atomic<<<(int)((th + 255) / 256), 256>>>(hrows, hcols, hvals, sup2, out2, nnz_h);

    int n4 = out_size / 4;
    epilogue<<<(n4 + 255) / 256, 256>>>(out, bias, n4);
}

// round 2
// speedup vs baseline: 1.4431x; 1.4431x over previous
#include <cuda_runtime.h>
#include <cuda_fp16.h>
#include <cstdint>

#define D 64
#define N_NODES_C  20000
#define N_HEDGES_C 400000

// Scratch: support = X @ W stored in fp16 (halves gather traffic; 51MB fits L2)
__device__ __half g_sup1[(size_t)N_NODES_C * D];
__device__ __half g_sup2[(size_t)N_HEDGES_C * D];

__device__ __forceinline__ void ffma2(unsigned long long& d,
                                      unsigned long long a,
                                      unsigned long long b) {
    asm("fma.rn.f32x2 %0, %1, %2, %0;" : "+l"(d) : "l"(a), "l"(b));
}
__device__ __forceinline__ unsigned long long pack2(float lo, float hi) {
    unsigned long long r;
    asm("mov.b64 %0, {%1, %2};" : "=l"(r) : "f"(lo), "f"(hi));
    return r;
}
__device__ __forceinline__ float2 unpack2(unsigned long long v) {
    float2 r;
    asm("mov.b64 {%0, %1}, %2;" : "=f"(r.x), "=f"(r.y) : "l"(v));
    return r;
}

// ---------------------------------------------------------------------------
// GEMM: out[M,64](fp16) = X[M,64] @ W[64,64], fp32 accumulate.
// 128-row tile / block, 256 threads; each thread: 4 rows x 8 cols.
// W smem reads amortized over 4 rows; packed f32x2 FMA.
// ---------------------------------------------------------------------------
__global__ void __launch_bounds__(256)
gemm_xw_h(const float* __restrict__ X, const float* __restrict__ W,
          __half* __restrict__ out, int M) {
    __shared__ __align__(16) float Ws[D][D];       // 16 KB
    __shared__ __align__(16) float Xs[128][68];    // pad 68: 272B rows (16B aligned)
    int t  = threadIdx.x;
    int m0 = blockIdx.x * 128;

    // Load W (4096 floats = 1024 float4)
    for (int i4 = t; i4 < D * D / 4; i4 += 256)
        *(float4*)&Ws[(i4 * 4) >> 6][(i4 * 4) & 63] = __ldg((const float4*)W + i4);
    // Load X tile (128x64 = 2048 float4), zero-pad out-of-range rows
    for (int i4 = t; i4 < 128 * D / 4; i4 += 256) {
        int r  = i4 >> 4;          // 16 float4 per row
        int c4 = (i4 & 15) * 4;
        int row = m0 + r;
        float4 v = (row < M) ? __ldg((const float4*)(X + (size_t)row * D + c4))
                             : make_float4(0.f, 0.f, 0.f, 0.f);
        *(float4*)&Xs[r][c4] = v;
    }
    __syncthreads();

    int rb = (t >> 3) * 4;       // base row in tile (0..124)
    int cg = (t & 7) * 8;        // col base (0..56)

    unsigned long long acc[4][4];
#pragma unroll
    for (int r = 0; r < 4; r++)
#pragma unroll
        for (int j = 0; j < 4; j++) acc[r][j] = pack2(0.f, 0.f);

#pragma unroll
    for (int k = 0; k < D; k++) {
        // 8 cols of W[k] as 4 packed f32x2 (type-punned 16B loads)
        ulonglong2 w0 = *(const ulonglong2*)&Ws[k][cg];
        ulonglong2 w1 = *(const ulonglong2*)&Ws[k][cg + 4];
#pragma unroll
        for (int r = 0; r < 4; r++) {
            float x = Xs[rb + r][k];
            unsigned long long xx = pack2(x, x);
            ffma2(acc[r][0], xx, w0.x);
            ffma2(acc[r][1], xx, w0.y);
            ffma2(acc[r][2], xx, w1.x);
            ffma2(acc[r][3], xx, w1.y);
        }
    }

#pragma unroll
    for (int r = 0; r < 4; r++) {
        int row = m0 + rb + r;
        if (row < M) {
            __half2 h[4];
#pragma unroll
            for (int j = 0; j < 4; j++) {
                float2 f = unpack2(acc[r][j]);
                h[j] = __float22half2_rn(f);
            }
            *(uint4*)(out + (size_t)row * D + cg) = *(uint4*)h;   // 16B store
        }
    }
}

// ---------------------------------------------------------------------------
// COO SpMM scatter: out[row] += val * dense[col]. 16 threads/nnz, 8B (4 half)
// gather per lane, vector red (no-return atomic). COO arrays streamed (ldcs)
// so they don't evict the hot fp16 dense rows from L2.
// ---------------------------------------------------------------------------
__global__ void spmm_atomic_h(const int* __restrict__ rows, const int* __restrict__ cols,
                              const float* __restrict__ vals, const __half* __restrict__ dense,
                              float* __restrict__ out, int nnz) {
    long long idx = (long long)blockIdx.x * blockDim.x + threadIdx.x;
    int nz = (int)(idx >> 4);
    int l4 = (int)(idx & 15);
    if (nz >= nnz) return;

    int   r = __ldcs(&rows[nz]);
    int   c = __ldcs(&cols[nz]);
    float v = __ldcs(&vals[nz]);

    uint2 p = __ldg((const uint2*)(dense + (size_t)c * D) + l4);
    float2 f0 = __half22float2(*(__half2*)&p.x);
    float2 f1 = __half22float2(*(__half2*)&p.y);

    float* dst = out + (size_t)r * D + (size_t)l4 * 4;
    asm volatile("red.global.add.v4.f32 [%0], {%1, %2, %3, %4};"
                 :: "l"(dst), "f"(v * f0.x), "f"(v * f0.y), "f"(v * f1.x), "f"(v * f1.y)
                 : "memory");
}

// ---------------------------------------------------------------------------
// Epilogue: out = relu(out) + bias, float4.
// ---------------------------------------------------------------------------
__global__ void epilogue(float* __restrict__ out, const float* __restrict__ bias, int n4) {
    int i = blockIdx.x * blockDim.x + threadIdx.x;
    if (i >= n4) return;
    float4 v = ((const float4*)out)[i];
    float4 b = __ldg((const float4*)bias + (i & 15));
    v.x = fmaxf(v.x, 0.f) + b.x;
    v.y = fmaxf(v.y, 0.f) + b.y;
    v.z = fmaxf(v.z, 0.f) + b.z;
    v.w = fmaxf(v.w, 0.f) + b.w;
    ((float4*)out)[i] = v;
}

// ---------------------------------------------------------------------------
extern "C" void kernel_launch(void* const* d_in, const int* in_sizes, int n_in,
                              void* d_out, int out_size) {
    const float* node_x = (const float*)d_in[0];
    const float* he_x   = (const float*)d_in[1];
    const int*   nrows  = (const int*)  d_in[2];
    const int*   ncols  = (const int*)  d_in[3];
    const float* nvals  = (const float*)d_in[4];
    const int*   hrows  = (const int*)  d_in[5];
    const int*   hcols  = (const int*)  d_in[6];
    const float* hvals  = (const float*)d_in[7];
    const float* W      = (const float*)d_in[8];
    const float* bias   = (const float*)d_in[9];

    int n_nodes = in_sizes[0] / D;
    int n_he    = in_sizes[1] / D;
    int nnz_n   = in_sizes[2];
    int nnz_h   = in_sizes[5];

    float* out  = (float*)d_out;
    float* out1 = out;
    float* out2 = out + (size_t)n_nodes * D;

    __half *sup1 = nullptr, *sup2 = nullptr;
    cudaGetSymbolAddress((void**)&sup1, g_sup1);
    cudaGetSymbolAddress((void**)&sup2, g_sup2);

    cudaMemsetAsync(d_out, 0, (size_t)out_size * sizeof(float), 0);

    gemm_xw_h<<<(n_nodes + 127) / 128, 256>>>(node_x, W, sup1, n_nodes);
    gemm_xw_h<<<(n_he    + 127) / 128, 256>>>(he_x,   W, sup2, n_he);

    long long tn = (long long)nnz_n * 16;
    spmm_atomic_h<<<(int)((tn + 255) / 256), 256>>>(nrows, ncols, nvals, sup1, out1, nnz_n);
    long long th = (long long)nnz_h * 16;
    spmm_atomic_h<<<(int)((th + 255) / 256), 256>>>(hrows, hcols, hvals, sup2, out2, nnz_h);

    int n4 = out_size / 4;
    epilogue<<<(n4 + 255) / 256, 256>>>(out, bias, n4);
}

// round 3
// speedup vs baseline: 1.9656x; 1.3621x over previous
#include <cuda_runtime.h>
#include <cuda_fp16.h>
#include <cstdint>

#define D 64
#define N_NODES_C  20000
#define N_HEDGES_C 400000
#define N_ROWS_TOT (N_NODES_C + N_HEDGES_C)
#define NNZ_TOT    (640000 + 6400000)

// Scratch (allocation-free rule: __device__ globals)
__device__ __half    g_sup1[(size_t)N_NODES_C * D];
__device__ __half    g_sup2[(size_t)N_HEDGES_C * D];
__device__ int       g_cnt[N_ROWS_TOT];      // per-row nnz count
__device__ int       g_rs[N_ROWS_TOT];       // row start (exclusive scan)
__device__ int       g_cur[N_ROWS_TOT];      // fill cursor (copy of g_rs)
__device__ long long g_fill[NNZ_TOT];        // packed (val<<32 | col) per nnz
__device__ int       g_bsums[256];           // scan block sums

// ===========================================================================
// GEMM: out[M,64](fp16) = X[M,64] @ W[64,64], fp32 accumulate.
// ===========================================================================
__device__ __forceinline__ void ffma2(unsigned long long& d,
                                      unsigned long long a,
                                      unsigned long long b) {
    asm("fma.rn.f32x2 %0, %1, %2, %0;" : "+l"(d) : "l"(a), "l"(b));
}
__device__ __forceinline__ unsigned long long pack2(float lo, float hi) {
    unsigned long long r;
    asm("mov.b64 %0, {%1, %2};" : "=l"(r) : "f"(lo), "f"(hi));
    return r;
}
__device__ __forceinline__ float2 unpack2(unsigned long long v) {
    float2 r;
    asm("mov.b64 {%0, %1}, %2;" : "=f"(r.x), "=f"(r.y) : "l"(v));
    return r;
}

__global__ void __launch_bounds__(256)
gemm_xw_h(const float* __restrict__ X, const float* __restrict__ W,
          __half* __restrict__ out, int M) {
    __shared__ __align__(16) float Ws[D][D];
    __shared__ __align__(16) float Xs[128][68];
    int t  = threadIdx.x;
    int m0 = blockIdx.x * 128;

    for (int i4 = t; i4 < D * D / 4; i4 += 256)
        *(float4*)&Ws[(i4 * 4) >> 6][(i4 * 4) & 63] = __ldg((const float4*)W + i4);
    for (int i4 = t; i4 < 128 * D / 4; i4 += 256) {
        int r  = i4 >> 4;
        int c4 = (i4 & 15) * 4;
        int row = m0 + r;
        float4 v = (row < M) ? __ldg((const float4*)(X + (size_t)row * D + c4))
                             : make_float4(0.f, 0.f, 0.f, 0.f);
        *(float4*)&Xs[r][c4] = v;
    }
    __syncthreads();

    int rb = (t >> 3) * 4;
    int cg = (t & 7) * 8;

    unsigned long long acc[4][4];
#pragma unroll
    for (int r = 0; r < 4; r++)
#pragma unroll
        for (int j = 0; j < 4; j++) acc[r][j] = pack2(0.f, 0.f);

#pragma unroll
    for (int k = 0; k < D; k++) {
        ulonglong2 w0 = *(const ulonglong2*)&Ws[k][cg];
        ulonglong2 w1 = *(const ulonglong2*)&Ws[k][cg + 4];
#pragma unroll
        for (int r = 0; r < 4; r++) {
            float x = Xs[rb + r][k];
            unsigned long long xx = pack2(x, x);
            ffma2(acc[r][0], xx, w0.x);
            ffma2(acc[r][1], xx, w0.y);
            ffma2(acc[r][2], xx, w1.x);
            ffma2(acc[r][3], xx, w1.y);
        }
    }

#pragma unroll
    for (int r = 0; r < 4; r++) {
        int row = m0 + rb + r;
        if (row < M) {
            __half2 h[4];
#pragma unroll
            for (int j = 0; j < 4; j++) {
                float2 f = unpack2(acc[r][j]);
                h[j] = __float22half2_rn(f);
            }
            *(uint4*)(out + (size_t)row * D + cg) = *(uint4*)h;
        }
    }
}

// ===========================================================================
// CSR build: histogram -> 3-phase exclusive scan -> ticketed fill
// ===========================================================================
__global__ void hist_k(const int* __restrict__ rows, int nnz, int base) {
    int i = blockIdx.x * blockDim.x + threadIdx.x;
    if (i < nnz) atomicAdd(&g_cnt[base + __ldcs(&rows[i])], 1);
}

// Each block sums a 4096-element chunk of g_cnt -> g_bsums[block]
__global__ void __launch_bounds__(256) scanA_k(int n) {
    __shared__ int sm[256];
    int b = blockIdx.x, t = threadIdx.x;
    int base = b * 4096 + t * 16;
    int s = 0;
#pragma unroll
    for (int k = 0; k < 16; k++) {
        int i = base + k;
        if (i < n) s += g_cnt[i];
    }
    sm[t] = s;
    __syncthreads();
    for (int o = 128; o > 0; o >>= 1) {
        if (t < o) sm[t] += sm[t + o];
        __syncthreads();
    }
    if (t == 0) g_bsums[b] = sm[0];
}

// Exclusive scan of g_bsums (nb <= 256), single block.
__global__ void __launch_bounds__(256) scanB_k(int nb) {
    __shared__ int sm[256];
    int t = threadIdx.x;
    int v = (t < nb) ? g_bsums[t] : 0;
    sm[t] = v;
    __syncthreads();
    for (int o = 1; o < 256; o <<= 1) {
        int x = (t >= o) ? sm[t - o] : 0;
        __syncthreads();
        sm[t] += x;
        __syncthreads();
    }
    if (t < nb) g_bsums[t] = sm[t] - v;   // exclusive
}

// Final pass: per-chunk exclusive scan + chunk offset -> g_rs, g_cur
__global__ void __launch_bounds__(256) scanC_k(int n) {
    __shared__ int sm[256];
    int b = blockIdx.x, t = threadIdx.x;
    int base = b * 4096 + t * 16;
    int loc[16];
    int s = 0;
#pragma unroll
    for (int k = 0; k < 16; k++) {
        int i = base + k;
        loc[k] = (i < n) ? g_cnt[i] : 0;
        s += loc[k];
    }
    sm[t] = s;
    __syncthreads();
    for (int o = 1; o < 256; o <<= 1) {
        int x = (t >= o) ? sm[t - o] : 0;
        __syncthreads();
        sm[t] += x;
        __syncthreads();
    }
    int off = g_bsums[b] + sm[t] - s;   // exclusive prefix for this thread
    int run = 0;
#pragma unroll
    for (int k = 0; k < 16; k++) {
        int i = base + k;
        if (i < n) {
            g_rs[i]  = off + run;
            g_cur[i] = off + run;
            run += loc[k];
        }
    }
}

__global__ void fill_k(const int* __restrict__ rows, const int* __restrict__ cols,
                       const float* __restrict__ vals, int nnz, int base) {
    int i = blockIdx.x * blockDim.x + threadIdx.x;
    if (i >= nnz) return;
    int r   = base + __ldcs(&rows[i]);
    int pos = atomicAdd(&g_cur[r], 1);
    long long e = ((long long)__float_as_int(__ldcs(&vals[i])) << 32)
                | (unsigned int)__ldcs(&cols[i]);
    g_fill[pos] = e;
}

// ===========================================================================
// CSR SpMM: one warp per output row. Per nnz: coalesced 128B gather of the
// fp16 dense row (half2 per lane), FMA into 2 regs/lane. Fused relu+bias,
// single coalesced float2 store per lane. No float atomics anywhere.
// ===========================================================================
__global__ void __launch_bounds__(256)
spmm_csr(const __half* __restrict__ dense, const float* __restrict__ bias,
         float* __restrict__ out, int row_base, int nrows) {
    int w = blockIdx.x * 8 + (threadIdx.x >> 5);
    if (w >= nrows) return;
    int lane  = threadIdx.x & 31;
    int gr    = row_base + w;
    int start = __ldg(&g_rs[gr]);
    int cn    = __ldg(&g_cnt[gr]);

    float a0 = 0.f, a1 = 0.f, b0 = 0.f, b1 = 0.f;

    for (int bb = 0; bb < cn; bb += 32) {
        int m = min(cn - bb, 32);
        long long e = (lane < m) ? __ldcs(&g_fill[start + bb + lane]) : 0;
        int j = 0;
        for (; j + 1 < m; j += 2) {
            long long e0 = __shfl_sync(0xffffffffu, e, j);
            long long e1 = __shfl_sync(0xffffffffu, e, j + 1);
            int   c0 = (int)(unsigned int)e0;
            int   c1 = (int)(unsigned int)e1;
            float v0 = __int_as_float((int)(e0 >> 32));
            float v1 = __int_as_float((int)(e1 >> 32));
            __half2 h0 = __ldg((const __half2*)(dense + (size_t)c0 * D) + lane);
            __half2 h1 = __ldg((const __half2*)(dense + (size_t)c1 * D) + lane);
            float2 f0 = __half22float2(h0);
            float2 f1 = __half22float2(h1);
            a0 += v0 * f0.x; a1 += v0 * f0.y;
            b0 += v1 * f1.x; b1 += v1 * f1.y;
        }
        if (j < m) {
            long long e0 = __shfl_sync(0xffffffffu, e, j);
            int   c0 = (int)(unsigned int)e0;
            float v0 = __int_as_float((int)(e0 >> 32));
            __half2 h0 = __ldg((const __half2*)(dense + (size_t)c0 * D) + lane);
            float2 f0 = __half22float2(h0);
            a0 += v0 * f0.x; a1 += v0 * f0.y;
        }
    }
    a0 += b0; a1 += b1;

    float2 bs = __ldg((const float2*)bias + lane);
    float2 o;
    o.x = fmaxf(a0, 0.f) + bs.x;
    o.y = fmaxf(a1, 0.f) + bs.y;
    *((float2*)(out + (size_t)w * D) + lane) = o;
}

// ===========================================================================
extern "C" void kernel_launch(void* const* d_in, const int* in_sizes, int n_in,
                              void* d_out, int out_size) {
    const float* node_x = (const float*)d_in[0];
    const float* he_x   = (const float*)d_in[1];
    const int*   nrows  = (const int*)  d_in[2];
    const int*   ncols  = (const int*)  d_in[3];
    const float* nvals  = (const float*)d_in[4];
    const int*   hrows  = (const int*)  d_in[5];
    const int*   hcols  = (const int*)  d_in[6];
    const float* hvals  = (const float*)d_in[7];
    const float* W      = (const float*)d_in[8];
    const float* bias   = (const float*)d_in[9];

    int n_nodes = in_sizes[0] / D;
    int n_he    = in_sizes[1] / D;
    int nnz_n   = in_sizes[2];
    int nnz_h   = in_sizes[5];
    int n_rows  = n_nodes + n_he;
    int nb      = (n_rows + 4095) / 4096;

    float* out1 = (float*)d_out;
    float* out2 = out1 + (size_t)n_nodes * D;

    __half* sup1; __half* sup2; int* cnt;
    cudaGetSymbolAddress((void**)&sup1, g_sup1);
    cudaGetSymbolAddress((void**)&sup2, g_sup2);
    cudaGetSymbolAddress((void**)&cnt,  g_cnt);

    // --- CSR build ---
    cudaMemsetAsync(cnt, 0, (size_t)n_rows * sizeof(int), 0);
    hist_k<<<(nnz_n + 255) / 256, 256>>>(nrows, nnz_n, 0);
    hist_k<<<(nnz_h + 255) / 256, 256>>>(hrows, nnz_h, n_nodes);
    scanA_k<<<nb, 256>>>(n_rows);
    scanB_k<<<1, 256>>>(nb);
    scanC_k<<<nb, 256>>>(n_rows);
    fill_k<<<(nnz_n + 255) / 256, 256>>>(nrows, ncols, nvals, nnz_n, 0);
    fill_k<<<(nnz_h + 255) / 256, 256>>>(hrows, hcols, hvals, nnz_h, n_nodes);

    // --- dense GEMMs (independent of CSR build, same stream) ---
    gemm_xw_h<<<(n_nodes + 127) / 128, 256>>>(node_x, W, sup1, n_nodes);
    gemm_xw_h<<<(n_he    + 127) / 128, 256>>>(he_x,   W, sup2, n_he);

    // --- CSR SpMM with fused relu+bias (covers every row, incl. empties) ---
    spmm_csr<<<(n_nodes + 7) / 8, 256>>>(sup1, bias, out1, 0,       n_nodes);
    spmm_csr<<<(n_he    + 7) / 8, 256>>>(sup2, bias, out2, n_nodes, n_he);
}